// round 11
// baseline (speedup 1.0000x reference)
#include <cuda_runtime.h>
#include <cuda_fp16.h>
#include <cstdint>

#define BB   32
#define SS   2048
#define ND   1024

// Scratch (allocation-free rule: __device__ globals)
__device__ float  g_scores[BB * SS];
__device__ float  g_decb[BB * ND];
__device__ __half g_Bth[ND * ND];         // W_enc^T fp16: Bth[n][k] = W[1024+k][n]
__device__ __half g_ench[BB * SS * ND];   // encoder_outputs in fp16

// ---------------------------------------------------------------- helpers
__device__ __forceinline__ float fast_tanh(float x) {
    float y;
    asm("tanh.approx.f32 %0, %1;" : "=f"(y) : "f"(x));
    return y;
}
__device__ __forceinline__ uint32_t smem_u32(const void* p) {
    uint32_t a;
    asm("{ .reg .u64 t; cvta.to.shared.u64 t, %1; cvt.u32.u64 %0, t; }" : "=r"(a) : "l"(p));
    return a;
}

// ---------------------------------------------------------------------------
// Kernel P: fused prologue.
//   blocks [0,8192)    : convert enc fp32 -> g_ench fp16
//   blocks [8192,9216) : transpose W_enc -> g_Bth fp16
//   blocks [9216,9344) : dec_base = dh @ W_dec + b_attn; zero scratch + ctx
// ---------------------------------------------------------------------------
__global__ void pre_kernel(const float* __restrict__ enc,
                           const float* __restrict__ W,
                           const float* __restrict__ dh,
                           const float* __restrict__ b_attn,
                           float* __restrict__ out_ctx) {
    __shared__ float shb[1088];
    const int bid = blockIdx.x;
    const int tid = threadIdx.x;

    if (bid < 8192) {
        const uint32_t t = bid * 256 + tid;
        uint2* outp = (uint2*)g_ench;
#pragma unroll
        for (int i = 0; i < 8; i++) {
            const uint32_t idx = t + (uint32_t)i * (8192 * 256);
            const float4 v = *(const float4*)(enc + (size_t)idx * 4);
            __half2 h0 = __floats2half2_rn(v.x, v.y);
            __half2 h1 = __floats2half2_rn(v.z, v.w);
            uint2 o;
            o.x = *(uint32_t*)&h0;
            o.y = *(uint32_t*)&h1;
            outp[idx] = o;
        }
    } else if (bid < 9216) {
        const int bid2 = bid - 8192;
        const int kb = (bid2 & 31) * 32, nb = (bid2 >> 5) * 32;
        const int tx = tid & 31, ty = tid >> 5;           // ty 0..7
        float (*t)[33] = (float(*)[33])shb;
#pragma unroll
        for (int i = 0; i < 32; i += 8)
            t[ty + i][tx] = W[(size_t)(1024 + kb + ty + i) * 1024 + nb + tx];
        __syncthreads();
#pragma unroll
        for (int i = 0; i < 32; i += 8)
            g_Bth[(size_t)(nb + ty + i) * 1024 + kb + tx] = __float2half_rn(t[tx][ty + i]);
    } else {
        const int bid3 = bid - 9216;                      // 0..127
        const int b = bid3 >> 2, dc = bid3 & 3;

        for (int i = bid3 * 256 + tid; i < BB * SS; i += 128 * 256) g_scores[i] = 0.f;
        for (int i = bid3 * 256 + tid; i < BB * ND; i += 128 * 256) out_ctx[i] = 0.f;

        for (int i = tid; i < ND; i += 256) shb[i] = dh[b * ND + i];
        __syncthreads();

        const int d0 = dc * 256 + tid;
        float a = b_attn[d0];
#pragma unroll 8
        for (int e = 0; e < ND; e++)
            a += shb[e] * W[(size_t)e * ND + d0];
        g_decb[b * ND + d0] = a;
    }
}

// ---------------------------------------------------------------------------
// Kernel 2: enc_proj GEMM, fp16 mma.sync m16n8k16, 128M x 256N tile, BK=64,
//   512 threads (16 warps, 4x4), 3-stage cp.async ring (144KB), ONE sync per
//   BK=64, FULL unroll (16 iters), fused tanh + v-dot.
//   Stage (48KB) = A0(8K) A1(8K) B0(16K) B1(16K); panels have 64B rows
//   (32 halfs) -> conflict-free LDS.128 fragment loads.
//   Ring safety identical to R8 (wait_group 1, sync, prefetch kt+2).
//   K-permutation identical on A and B (exact): thread k-window = (lane&3)*8.
// ---------------------------------------------------------------------------
#define STGB      49152                    // 48 KB per stage
#define BOFP      16384                    // B region offset inside stage
#define GEMM_SMEM (3 * STGB)               // 144 KB

__global__ __launch_bounds__(512, 1) void score_gemm(const float* __restrict__ vw) {
    extern __shared__ char smc[];
    const uint32_t sb = smem_u32(smc);
    const int tid  = threadIdx.x;
    const int lane = tid & 31;
    const int warp = tid >> 5;
    const int wm   = warp >> 2;              // 0..3  (M rows wm*32..+32)
    const int wn   = warp & 3;               // 0..3  (N cols wn*64..+64)
    const int n0   = blockIdx.x * 256;
    const int m0   = blockIdx.y * 128;

    // cp.async mapping (16B chunks): rr = tid>>3, cc = tid&7
    //   A: 1024 chunks, 2/thread (i=0..1, row += 64)
    //   B: 2048 chunks, 4/thread (i=0..3, row += 64)
    const int rr = tid >> 3, cc = tid & 7;
    const char* pa = (const char*)(g_ench + (size_t)(m0 + rr) * 1024 + cc * 8);
    const char* pb = (const char*)(g_Bth  + (size_t)(n0 + rr) * 1024 + cc * 8);
    const uint32_t dA = sb + (uint32_t)((cc >> 2) * 8192 + rr * 64 + (cc & 3) * 16);
    const uint32_t dB = sb + BOFP + (uint32_t)((cc >> 2) * 16384 + rr * 64 + (cc & 3) * 16);
    // per-i: src += 64 rows = 131072 B ; dst += 64*64 = 4096 B

#define LOAD_STAGE(kt, st)                                                      \
    do {                                                                        \
        const uint32_t so = (uint32_t)(st) * STGB;                              \
        const int kb_ = (kt) * 128;  /* BK=64 halfs = 128 B */                  \
        _Pragma("unroll")                                                       \
        for (int i_ = 0; i_ < 2; i_++)                                          \
            asm volatile("cp.async.cg.shared.global [%0], [%1], 16;"            \
                         :: "r"(dA + so + i_ * 4096), "l"(pa + kb_ + i_ * 131072)); \
        _Pragma("unroll")                                                       \
        for (int i_ = 0; i_ < 4; i_++)                                          \
            asm volatile("cp.async.cg.shared.global [%0], [%1], 16;"            \
                         :: "r"(dB + so + i_ * 4096), "l"(pb + kb_ + i_ * 131072)); \
    } while (0)

    float acc[2][8][4];
#pragma unroll
    for (int i = 0; i < 2; i++)
#pragma unroll
        for (int j = 0; j < 8; j++)
#pragma unroll
            for (int c = 0; c < 4; c++) acc[i][j][c] = 0.f;

    // preamble: stages 0,1 in flight
    LOAD_STAGE(0, 0);
    asm volatile("cp.async.commit_group;" ::: "memory");
    LOAD_STAGE(1, 1);
    asm volatile("cp.async.commit_group;" ::: "memory");

    const uint32_t koff = (lane & 3) * 16;
    const uint32_t aoff = (uint32_t)(wm * 32 + (lane >> 2)) * 64 + koff;
    const uint32_t boff = (uint32_t)(wn * 64 + (lane >> 2)) * 64 + koff;

#pragma unroll
    for (int kt = 0; kt < 16; kt++) {
        const int st = kt % 3;
        asm volatile("cp.async.wait_group 1;" ::: "memory");
        __syncthreads();

        // prefetch stage kt+2 into slot (kt+2)%3 (freed by iter kt-1)
        if (kt < 14) LOAD_STAGE(kt + 2, (kt + 2) % 3);
        asm volatile("cp.async.commit_group;" ::: "memory");

        const uint32_t Astg = sb + (uint32_t)st * STGB;

#pragma unroll
        for (int s = 0; s < 2; s++) {           // two k32 panels
            const uint32_t Apan = Astg + (uint32_t)s * 8192 + aoff;
            const uint32_t Bpan = Astg + BOFP + (uint32_t)s * 16384 + boff;

            uint32_t ah[4][4];
#pragma unroll
            for (int rdx = 0; rdx < 4; rdx++)
                asm volatile("ld.shared.v4.u32 {%0,%1,%2,%3}, [%4];"
                             : "=r"(ah[rdx][0]), "=r"(ah[rdx][1]),
                               "=r"(ah[rdx][2]), "=r"(ah[rdx][3])
                             : "r"(Apan + rdx * 512));

#pragma unroll
            for (int jh = 0; jh < 2; jh++) {
                uint32_t bh[4][4];
#pragma unroll
                for (int j = 0; j < 4; j++)
                    asm volatile("ld.shared.v4.u32 {%0,%1,%2,%3}, [%4];"
                                 : "=r"(bh[j][0]), "=r"(bh[j][1]),
                                   "=r"(bh[j][2]), "=r"(bh[j][3])
                                 : "r"(Bpan + (jh * 4 + j) * 512));
#pragma unroll
                for (int i = 0; i < 2; i++)
#pragma unroll
                    for (int j = 0; j < 4; j++)
#pragma unroll
                        for (int u = 0; u < 2; u++) {
                            const int jj = jh * 4 + j;
                            asm volatile(
                                "mma.sync.aligned.m16n8k16.row.col.f32.f16.f16.f32 "
                                "{%0,%1,%2,%3}, {%4,%5,%6,%7}, {%8,%9}, {%0,%1,%2,%3};"
                                : "+f"(acc[i][jj][0]), "+f"(acc[i][jj][1]),
                                  "+f"(acc[i][jj][2]), "+f"(acc[i][jj][3])
                                : "r"(ah[2 * i][2 * u]), "r"(ah[2 * i + 1][2 * u]),
                                  "r"(ah[2 * i][2 * u + 1]), "r"(ah[2 * i + 1][2 * u + 1]),
                                  "r"(bh[j][2 * u]), "r"(bh[j][2 * u + 1]));
                        }
            }
        }
    }
#undef LOAD_STAGE

    // Epilogue: energy = tanh(acc + dec_base[b][col]); score partial = energy . v_w
    const int b = m0 >> 11;
    float eadd[16], vv[16];
#pragma unroll
    for (int j = 0; j < 8; j++)
#pragma unroll
        for (int c = 0; c < 2; c++) {
            const int col = n0 + wn * 64 + j * 8 + (lane & 3) * 2 + c;
            eadd[j * 2 + c] = g_decb[b * ND + col];
            vv[j * 2 + c]   = vw[col];
        }

#pragma unroll
    for (int i = 0; i < 2; i++)
#pragma unroll
        for (int h = 0; h < 2; h++) {
            float p = 0.f;
#pragma unroll
            for (int j = 0; j < 8; j++)
#pragma unroll
                for (int c = 0; c < 2; c++)
                    p += fast_tanh(acc[i][j][h * 2 + c] + eadd[j * 2 + c]) * vv[j * 2 + c];
            p += __shfl_xor_sync(0xffffffffu, p, 1);
            p += __shfl_xor_sync(0xffffffffu, p, 2);
            if ((lane & 3) == 0) {
                const int row = m0 + wm * 32 + i * 16 + h * 8 + (lane >> 2);
                atomicAdd(&g_scores[row], p);
            }
        }
}

// ---------------------------------------------------------------------------
// Kernel 3: masked softmax over S per batch
// ---------------------------------------------------------------------------
__global__ void softmax_kernel(const int* __restrict__ mask,
                               float* __restrict__ out_w) {
    const int b = blockIdx.x;
    const int tid = threadIdx.x;
    __shared__ float red[256];

    float ls[8];
#pragma unroll
    for (int i = 0; i < 8; i++) {
        const int s = tid + i * 256;
        const float sc = g_scores[b * SS + s];
        ls[i] = (mask[b * SS + s] == 0) ? -1e9f : sc;
    }
    float mx = ls[0];
#pragma unroll
    for (int i = 1; i < 8; i++) mx = fmaxf(mx, ls[i]);
    red[tid] = mx;
    __syncthreads();
    for (int off = 128; off > 0; off >>= 1) {
        if (tid < off) red[tid] = fmaxf(red[tid], red[tid + off]);
        __syncthreads();
    }
    mx = red[0];
    __syncthreads();

    float ex[8];
    float sum = 0.f;
#pragma unroll
    for (int i = 0; i < 8; i++) {
        ex[i] = __expf(ls[i] - mx);
        sum += ex[i];
    }
    red[tid] = sum;
    __syncthreads();
    for (int off = 128; off > 0; off >>= 1) {
        if (tid < off) red[tid] += red[tid + off];
        __syncthreads();
    }
    const float inv = 1.f / red[0];
#pragma unroll
    for (int i = 0; i < 8; i++)
        out_w[b * SS + tid + i * 256] = ex[i] * inv;
}

// ---------------------------------------------------------------------------
// Kernel 4: context = attn_weights @ encoder_outputs (fp16 enc, fp32 accum)
// ---------------------------------------------------------------------------
__global__ void context_kernel(const float* __restrict__ w,
                               float* __restrict__ ctx) {
    const int b = blockIdx.y;
    const int ch = blockIdx.x;
    const int tid = threadIdx.x;
    __shared__ float ws[128];
    const int s0 = ch * 128;
    if (tid < 128) ws[tid] = w[b * SS + s0 + tid];
    __syncthreads();

    float ax = 0.f, ay = 0.f, az = 0.f, aw = 0.f;
    const __half* base = g_ench + ((size_t)b * SS + s0) * 1024 + tid * 4;
#pragma unroll 4
    for (int s = 0; s < 128; s++) {
        const uint2 u = *(const uint2*)(base + (size_t)s * 1024);
        const float2 f01 = __half22float2(*(const __half2*)&u.x);
        const float2 f23 = __half22float2(*(const __half2*)&u.y);
        const float wv = ws[s];
        ax += wv * f01.x;
        ay += wv * f01.y;
        az += wv * f23.x;
        aw += wv * f23.y;
    }
    float* o = ctx + b * ND + tid * 4;
    atomicAdd(o + 0, ax);
    atomicAdd(o + 1, ay);
    atomicAdd(o + 2, az);
    atomicAdd(o + 3, aw);
}

// ---------------------------------------------------------------------------
extern "C" void kernel_launch(void* const* d_in, const int* in_sizes, int n_in,
                              void* d_out, int out_size) {
    const float* dh   = (const float*)d_in[0];   // (32, 1024)
    const float* enc  = (const float*)d_in[1];   // (32, 2048, 1024)
    const int*   mask = (const int*)d_in[2];     // (32, 2048)
    const float* W    = (const float*)d_in[3];   // (2048, 1024)
    const float* ba   = (const float*)d_in[4];   // (1024,)
    const float* vw   = (const float*)d_in[5];   // (1024,)

    float* out  = (float*)d_out;
    float* ctx  = out;                 // (32, 1024)
    float* attw = out + BB * ND;       // (32, 2048)

    cudaFuncSetAttribute(score_gemm, cudaFuncAttributeMaxDynamicSharedMemorySize, GEMM_SMEM);

    pre_kernel<<<9344, 256>>>(enc, W, dh, ba, ctx);
    score_gemm<<<dim3(4, 512), 512, GEMM_SMEM>>>(vw);
    softmax_kernel<<<32, 256>>>(mask, attw);
    context_kernel<<<dim3(16, 32), 256>>>(attw, ctx);
}

// round 12
// speedup vs baseline: 1.0722x; 1.0722x over previous
#include <cuda_runtime.h>
#include <cuda_fp16.h>
#include <cstdint>

#define BB   32
#define SS   2048
#define ND   1024

// Scratch (allocation-free rule: __device__ globals)
__device__ float  g_scores[BB * SS];
__device__ float  g_decb[BB * ND];
__device__ __half g_Bth[ND * ND];         // W_enc^T fp16: Bth[n][k] = W[1024+k][n]
__device__ __half g_ench[BB * SS * ND];   // encoder_outputs in fp16

// ---------------------------------------------------------------- helpers
__device__ __forceinline__ float fast_tanh(float x) {
    float y;
    asm("tanh.approx.f32 %0, %1;" : "=f"(y) : "f"(x));
    return y;
}
__device__ __forceinline__ uint32_t smem_u32(const void* p) {
    uint32_t a;
    asm("{ .reg .u64 t; cvta.to.shared.u64 t, %1; cvt.u32.u64 %0, t; }" : "=r"(a) : "l"(p));
    return a;
}

// ---------------------------------------------------------------------------
// Kernel P: fused prologue.
//   blocks [0,8192)    : convert enc fp32 -> g_ench fp16
//   blocks [8192,9216) : transpose W_enc -> g_Bth fp16
//   blocks [9216,9344) : dec_base = dh @ W_dec + b_attn; zero scratch + ctx
// ---------------------------------------------------------------------------
__global__ void pre_kernel(const float* __restrict__ enc,
                           const float* __restrict__ W,
                           const float* __restrict__ dh,
                           const float* __restrict__ b_attn,
                           float* __restrict__ out_ctx) {
    __shared__ float shb[1088];
    const int bid = blockIdx.x;
    const int tid = threadIdx.x;

    if (bid < 8192) {
        const uint32_t t = bid * 256 + tid;
        uint2* outp = (uint2*)g_ench;
#pragma unroll
        for (int i = 0; i < 8; i++) {
            const uint32_t idx = t + (uint32_t)i * (8192 * 256);
            const float4 v = *(const float4*)(enc + (size_t)idx * 4);
            __half2 h0 = __floats2half2_rn(v.x, v.y);
            __half2 h1 = __floats2half2_rn(v.z, v.w);
            uint2 o;
            o.x = *(uint32_t*)&h0;
            o.y = *(uint32_t*)&h1;
            outp[idx] = o;
        }
    } else if (bid < 9216) {
        const int bid2 = bid - 8192;
        const int kb = (bid2 & 31) * 32, nb = (bid2 >> 5) * 32;
        const int tx = tid & 31, ty = tid >> 5;           // ty 0..7
        float (*t)[33] = (float(*)[33])shb;
#pragma unroll
        for (int i = 0; i < 32; i += 8)
            t[ty + i][tx] = W[(size_t)(1024 + kb + ty + i) * 1024 + nb + tx];
        __syncthreads();
#pragma unroll
        for (int i = 0; i < 32; i += 8)
            g_Bth[(size_t)(nb + ty + i) * 1024 + kb + tx] = __float2half_rn(t[tx][ty + i]);
    } else {
        const int bid3 = bid - 9216;                      // 0..127
        const int b = bid3 >> 2, dc = bid3 & 3;

        for (int i = bid3 * 256 + tid; i < BB * SS; i += 128 * 256) g_scores[i] = 0.f;
        for (int i = bid3 * 256 + tid; i < BB * ND; i += 128 * 256) out_ctx[i] = 0.f;

        for (int i = tid; i < ND; i += 256) shb[i] = dh[b * ND + i];
        __syncthreads();

        const int d0 = dc * 256 + tid;
        float a = b_attn[d0];
#pragma unroll 8
        for (int e = 0; e < ND; e++)
            a += shb[e] * W[(size_t)e * ND + d0];
        g_decb[b * ND + d0] = a;
    }
}

// ---------------------------------------------------------------------------
// Kernel 2: enc_proj GEMM, fp16 mma.sync m16n8k16, 128x128 tile, BK=64,
//   3-stage cp.async ring (96KB), ONE sync per BK=64, FULL unroll (16 iters),
//   fused tanh + v-dot.   (R10 configuration — best measured)
// ---------------------------------------------------------------------------
#define PAN       8192
#define STGB      (4 * PAN)                // 32 KB per stage
#define GEMM_SMEM (3 * STGB)               // 96 KB

__global__ __launch_bounds__(256, 2) void score_gemm(const float* __restrict__ vw) {
    extern __shared__ char smc[];
    const uint32_t sb = smem_u32(smc);
    const int tid  = threadIdx.x;
    const int lane = tid & 31;
    const int warp = tid >> 5;
    const int wm   = warp >> 1;              // 0..3
    const int wn   = warp & 1;               // 0..1
    const int n0   = blockIdx.x * 128;
    const int m0   = blockIdx.y * 128;

    const int rr = tid >> 3, cc = tid & 7;
    const char* pa = (const char*)(g_ench + (size_t)(m0 + rr) * 1024 + cc * 8);
    const char* pb = (const char*)(g_Bth  + (size_t)(n0 + rr) * 1024 + cc * 8);
    const uint32_t dA = sb + (uint32_t)((cc >> 2) * PAN + rr * 64 + (cc & 3) * 16);
    const uint32_t dB = dA + 2 * PAN;

#define LOAD_STAGE(kt, st)                                                      \
    do {                                                                        \
        const uint32_t so = (uint32_t)(st) * STGB;                              \
        const int kb_ = (kt) * 128;  /* BK=64 halfs = 128 B */                  \
        _Pragma("unroll")                                                       \
        for (int i_ = 0; i_ < 4; i_++) {                                        \
            asm volatile("cp.async.cg.shared.global [%0], [%1], 16;"            \
                         :: "r"(dA + so + i_ * 2048), "l"(pa + kb_ + i_ * 65536)); \
            asm volatile("cp.async.cg.shared.global [%0], [%1], 16;"            \
                         :: "r"(dB + so + i_ * 2048), "l"(pb + kb_ + i_ * 65536)); \
        }                                                                       \
    } while (0)

    float acc[2][8][4];
#pragma unroll
    for (int i = 0; i < 2; i++)
#pragma unroll
        for (int j = 0; j < 8; j++)
#pragma unroll
            for (int c = 0; c < 4; c++) acc[i][j][c] = 0.f;

    LOAD_STAGE(0, 0);
    asm volatile("cp.async.commit_group;" ::: "memory");
    LOAD_STAGE(1, 1);
    asm volatile("cp.async.commit_group;" ::: "memory");

    const uint32_t koff = (lane & 3) * 16;
    const uint32_t aoff = (uint32_t)(wm * 32 + (lane >> 2)) * 64 + koff;
    const uint32_t boff = (uint32_t)(wn * 64 + (lane >> 2)) * 64 + koff + 2 * PAN;

#pragma unroll
    for (int kt = 0; kt < 16; kt++) {
        const int st = kt % 3;
        asm volatile("cp.async.wait_group 1;" ::: "memory");
        __syncthreads();

        if (kt < 14) LOAD_STAGE(kt + 2, (kt + 2) % 3);
        asm volatile("cp.async.commit_group;" ::: "memory");

        const uint32_t Astg = sb + (uint32_t)st * STGB;

#pragma unroll
        for (int s = 0; s < 2; s++) {           // two k32 panels
            const uint32_t Asb = Astg + (uint32_t)s * PAN + aoff;
            const uint32_t Bsb = Astg + (uint32_t)s * PAN + boff;

            uint32_t ah[4][4];
#pragma unroll
            for (int rdx = 0; rdx < 4; rdx++)
                asm volatile("ld.shared.v4.u32 {%0,%1,%2,%3}, [%4];"
                             : "=r"(ah[rdx][0]), "=r"(ah[rdx][1]),
                               "=r"(ah[rdx][2]), "=r"(ah[rdx][3])
                             : "r"(Asb + rdx * 512));

#pragma unroll
            for (int jh = 0; jh < 2; jh++) {
                uint32_t bh[4][4];
#pragma unroll
                for (int j = 0; j < 4; j++)
                    asm volatile("ld.shared.v4.u32 {%0,%1,%2,%3}, [%4];"
                                 : "=r"(bh[j][0]), "=r"(bh[j][1]),
                                   "=r"(bh[j][2]), "=r"(bh[j][3])
                                 : "r"(Bsb + (jh * 4 + j) * 512));
#pragma unroll
                for (int i = 0; i < 2; i++)
#pragma unroll
                    for (int j = 0; j < 4; j++)
#pragma unroll
                        for (int u = 0; u < 2; u++) {
                            const int jj = jh * 4 + j;
                            asm volatile(
                                "mma.sync.aligned.m16n8k16.row.col.f32.f16.f16.f32 "
                                "{%0,%1,%2,%3}, {%4,%5,%6,%7}, {%8,%9}, {%0,%1,%2,%3};"
                                : "+f"(acc[i][jj][0]), "+f"(acc[i][jj][1]),
                                  "+f"(acc[i][jj][2]), "+f"(acc[i][jj][3])
                                : "r"(ah[2 * i][2 * u]), "r"(ah[2 * i + 1][2 * u]),
                                  "r"(ah[2 * i][2 * u + 1]), "r"(ah[2 * i + 1][2 * u + 1]),
                                  "r"(bh[j][2 * u]), "r"(bh[j][2 * u + 1]));
                        }
            }
        }
    }
#undef LOAD_STAGE

    // Epilogue: energy = tanh(acc + dec_base[b][col]); score partial = energy . v_w
    const int b = m0 >> 11;
    float eadd[16], vv[16];
#pragma unroll
    for (int j = 0; j < 8; j++)
#pragma unroll
        for (int c = 0; c < 2; c++) {
            const int col = n0 + wn * 64 + j * 8 + (lane & 3) * 2 + c;
            eadd[j * 2 + c] = g_decb[b * ND + col];
            vv[j * 2 + c]   = vw[col];
        }

#pragma unroll
    for (int i = 0; i < 2; i++)
#pragma unroll
        for (int h = 0; h < 2; h++) {
            float p = 0.f;
#pragma unroll
            for (int j = 0; j < 8; j++)
#pragma unroll
                for (int c = 0; c < 2; c++)
                    p += fast_tanh(acc[i][j][h * 2 + c] + eadd[j * 2 + c]) * vv[j * 2 + c];
            p += __shfl_xor_sync(0xffffffffu, p, 1);
            p += __shfl_xor_sync(0xffffffffu, p, 2);
            if ((lane & 3) == 0) {
                const int row = m0 + wm * 32 + i * 16 + h * 8 + (lane >> 2);
                atomicAdd(&g_scores[row], p);
            }
        }
}

// ---------------------------------------------------------------------------
// Kernel 3: FUSED masked-softmax + context.
//   grid (16 s-chunks, 32 b), 256 threads.
//   Phase 1: every block redundantly computes the full softmax for batch b
//     (thread t owns s in [t*8, t*8+8)); the 16 threads owning this block's
//     chunk write attn_weights[b, ch*128 .. +128) and stash them in smem.
//   Phase 2: context partial for this chunk: thread (tid&127) covers 8 cols,
//     (tid>>7) picks the s-half; 16B loads; halves combined in smem; 
//     atomicAdd into ctx.
// ---------------------------------------------------------------------------
__global__ void softmax_context_kernel(const int* __restrict__ mask,
                                       float* __restrict__ attw,
                                       float* __restrict__ ctx) {
    const int b   = blockIdx.y;
    const int ch  = blockIdx.x;
    const int tid = threadIdx.x;
    __shared__ float red[256];
    __shared__ float ws[128];
    __shared__ float part[128 * 8];

    // ---- phase 1: full-row masked softmax (redundant per chunk-block)
    const int sbase = tid * 8;
    const float4 sv0 = *(const float4*)(g_scores + b * SS + sbase);
    const float4 sv1 = *(const float4*)(g_scores + b * SS + sbase + 4);
    const int4   mv0 = *(const int4*)(mask + b * SS + sbase);
    const int4   mv1 = *(const int4*)(mask + b * SS + sbase + 4);
    float ls[8];
    ls[0] = mv0.x ? sv0.x : -1e9f;
    ls[1] = mv0.y ? sv0.y : -1e9f;
    ls[2] = mv0.z ? sv0.z : -1e9f;
    ls[3] = mv0.w ? sv0.w : -1e9f;
    ls[4] = mv1.x ? sv1.x : -1e9f;
    ls[5] = mv1.y ? sv1.y : -1e9f;
    ls[6] = mv1.z ? sv1.z : -1e9f;
    ls[7] = mv1.w ? sv1.w : -1e9f;

    float mx = ls[0];
#pragma unroll
    for (int i = 1; i < 8; i++) mx = fmaxf(mx, ls[i]);
    red[tid] = mx;
    __syncthreads();
    for (int off = 128; off > 0; off >>= 1) {
        if (tid < off) red[tid] = fmaxf(red[tid], red[tid + off]);
        __syncthreads();
    }
    mx = red[0];
    __syncthreads();

    float ex[8];
    float sum = 0.f;
#pragma unroll
    for (int i = 0; i < 8; i++) {
        ex[i] = __expf(ls[i] - mx);
        sum += ex[i];
    }
    red[tid] = sum;
    __syncthreads();
    for (int off = 128; off > 0; off >>= 1) {
        if (tid < off) red[tid] += red[tid + off];
        __syncthreads();
    }
    const float inv = 1.f / red[0];

    // owning threads of this chunk write attw + smem weights
    if ((tid >> 4) == ch) {
        float4 lo = make_float4(ex[0] * inv, ex[1] * inv, ex[2] * inv, ex[3] * inv);
        float4 hi = make_float4(ex[4] * inv, ex[5] * inv, ex[6] * inv, ex[7] * inv);
        *(float4*)(attw + b * SS + sbase)     = lo;
        *(float4*)(attw + b * SS + sbase + 4) = hi;
        const int ls0 = sbase - ch * 128;     // 0..120
        *(float4*)(ws + ls0)     = lo;
        *(float4*)(ws + ls0 + 4) = hi;
    }
    __syncthreads();

    // ---- phase 2: context partial for chunk [ch*128, +128)
    const int colg = (tid & 127) * 8;
    const int sh   = tid >> 7;                // s-half 0/1
    const __half* base =
        g_ench + ((size_t)b * SS + ch * 128 + sh * 64) * 1024 + colg;

    float a0 = 0.f, a1 = 0.f, a2 = 0.f, a3 = 0.f;
    float a4 = 0.f, a5 = 0.f, a6 = 0.f, a7 = 0.f;
#pragma unroll 4
    for (int s = 0; s < 64; s++) {
        const uint4 u = *(const uint4*)(base + (size_t)s * 1024);
        const float wv = ws[sh * 64 + s];
        const float2 f0 = __half22float2(*(const __half2*)&u.x);
        const float2 f1 = __half22float2(*(const __half2*)&u.y);
        const float2 f2 = __half22float2(*(const __half2*)&u.z);
        const float2 f3 = __half22float2(*(const __half2*)&u.w);
        a0 += wv * f0.x; a1 += wv * f0.y;
        a2 += wv * f1.x; a3 += wv * f1.y;
        a4 += wv * f2.x; a5 += wv * f2.y;
        a6 += wv * f3.x; a7 += wv * f3.y;
    }

    if (sh == 1) {
        float* p = part + (tid & 127) * 8;
        p[0] = a0; p[1] = a1; p[2] = a2; p[3] = a3;
        p[4] = a4; p[5] = a5; p[6] = a6; p[7] = a7;
    }
    __syncthreads();
    if (sh == 0) {
        const float* p = part + tid * 8;
        float* o = ctx + b * ND + colg;
        atomicAdd(o + 0, a0 + p[0]);
        atomicAdd(o + 1, a1 + p[1]);
        atomicAdd(o + 2, a2 + p[2]);
        atomicAdd(o + 3, a3 + p[3]);
        atomicAdd(o + 4, a4 + p[4]);
        atomicAdd(o + 5, a5 + p[5]);
        atomicAdd(o + 6, a6 + p[6]);
        atomicAdd(o + 7, a7 + p[7]);
    }
}

// ---------------------------------------------------------------------------
extern "C" void kernel_launch(void* const* d_in, const int* in_sizes, int n_in,
                              void* d_out, int out_size) {
    const float* dh   = (const float*)d_in[0];   // (32, 1024)
    const float* enc  = (const float*)d_in[1];   // (32, 2048, 1024)
    const int*   mask = (const int*)d_in[2];     // (32, 2048)
    const float* W    = (const float*)d_in[3];   // (2048, 1024)
    const float* ba   = (const float*)d_in[4];   // (1024,)
    const float* vw   = (const float*)d_in[5];   // (1024,)

    float* out  = (float*)d_out;
    float* ctx  = out;                 // (32, 1024)
    float* attw = out + BB * ND;       // (32, 2048)

    cudaFuncSetAttribute(score_gemm, cudaFuncAttributeMaxDynamicSharedMemorySize, GEMM_SMEM);

    pre_kernel<<<9344, 256>>>(enc, W, dh, ba, ctx);
    score_gemm<<<dim3(8, 512), 256, GEMM_SMEM>>>(vw);
    softmax_context_kernel<<<dim3(16, 32), 256>>>(mask, attw, ctx);
}

// round 13
// speedup vs baseline: 1.1015x; 1.0274x over previous
#include <cuda_runtime.h>
#include <cuda_fp16.h>
#include <cstdint>

#define BB   32
#define SS   2048
#define ND   1024

// Scratch (allocation-free rule: __device__ globals)
__device__ float  g_scores[BB * SS];
__device__ float  g_decb[BB * ND];
__device__ __half g_Bth[ND * ND];         // W_enc^T fp16: Bth[n][k] = W[1024+k][n]
__device__ __half g_ench[BB * SS * ND];   // encoder_outputs in fp16

// ---------------------------------------------------------------- helpers
__device__ __forceinline__ float fast_tanh(float x) {
    float y;
    asm("tanh.approx.f32 %0, %1;" : "=f"(y) : "f"(x));
    return y;
}
__device__ __forceinline__ uint32_t smem_u32(const void* p) {
    uint32_t a;
    asm("{ .reg .u64 t; cvta.to.shared.u64 t, %1; cvt.u32.u64 %0, t; }" : "=r"(a) : "l"(p));
    return a;
}

// ---------------------------------------------------------------------------
// Kernel P: fused prologue (latency-bound branches FIRST so their tails hide
// under the bandwidth-bound convert wave).
//   blocks [0,128)     : dec_base = dh @ W_dec + b_attn; zero scratch + ctx
//   blocks [128,1152)  : transpose W_enc -> g_Bth fp16
//   blocks [1152,5248) : convert enc fp32 -> g_ench fp16 (32B-read/16B-write)
// ---------------------------------------------------------------------------
__global__ void pre_kernel(const float* __restrict__ enc,
                           const float* __restrict__ W,
                           const float* __restrict__ dh,
                           const float* __restrict__ b_attn,
                           float* __restrict__ out_ctx) {
    __shared__ float shb[1088];
    const int bid = blockIdx.x;
    const int tid = threadIdx.x;

    if (bid < 128) {
        const int b = bid >> 2, dc = bid & 3;

        for (int i = bid * 256 + tid; i < BB * SS; i += 128 * 256) g_scores[i] = 0.f;
        for (int i = bid * 256 + tid; i < BB * ND; i += 128 * 256) out_ctx[i] = 0.f;

        for (int i = tid; i < ND; i += 256) shb[i] = dh[b * ND + i];
        __syncthreads();

        const int d0 = dc * 256 + tid;
        float a = b_attn[d0];
#pragma unroll 8
        for (int e = 0; e < ND; e++)
            a += shb[e] * W[(size_t)e * ND + d0];
        g_decb[b * ND + d0] = a;
    } else if (bid < 1152) {
        const int bid2 = bid - 128;
        const int kb = (bid2 & 31) * 32, nb = (bid2 >> 5) * 32;
        const int tx = tid & 31, ty = tid >> 5;           // ty 0..7
        float (*t)[33] = (float(*)[33])shb;
#pragma unroll
        for (int i = 0; i < 32; i += 8)
            t[ty + i][tx] = W[(size_t)(1024 + kb + ty + i) * 1024 + nb + tx];
        __syncthreads();
#pragma unroll
        for (int i = 0; i < 32; i += 8)
            g_Bth[(size_t)(nb + ty + i) * 1024 + kb + tx] = __float2half_rn(t[tx][ty + i]);
    } else {
        // convert: 64M floats = 8M uint4 outputs; 4096 blocks x 256 thr x 8 iters
        const uint32_t t = (uint32_t)(bid - 1152) * 256 + tid;   // 0..1M-1
        uint4* outp = (uint4*)g_ench;
#pragma unroll
        for (int i = 0; i < 8; i++) {
            const uint32_t o4 = t + (uint32_t)i * (4096 * 256);  // uint4 index
            const float4 v0 = *(const float4*)(enc + (size_t)o4 * 8);
            const float4 v1 = *(const float4*)(enc + (size_t)o4 * 8 + 4);
            __half2 h0 = __floats2half2_rn(v0.x, v0.y);
            __half2 h1 = __floats2half2_rn(v0.z, v0.w);
            __half2 h2 = __floats2half2_rn(v1.x, v1.y);
            __half2 h3 = __floats2half2_rn(v1.z, v1.w);
            uint4 o;
            o.x = *(uint32_t*)&h0;
            o.y = *(uint32_t*)&h1;
            o.z = *(uint32_t*)&h2;
            o.w = *(uint32_t*)&h3;
            outp[o4] = o;
        }
    }
}

// ---------------------------------------------------------------------------
// Kernel 2: enc_proj GEMM, fp16 mma.sync m16n8k16, 128x128 tile, BK=64,
//   3-stage cp.async ring (96KB), ONE sync per BK=64, FULL unroll (16 iters),
//   fused tanh + v-dot.   (R10 configuration — best measured)
// ---------------------------------------------------------------------------
#define PAN       8192
#define STGB      (4 * PAN)                // 32 KB per stage
#define GEMM_SMEM (3 * STGB)               // 96 KB

__global__ __launch_bounds__(256, 2) void score_gemm(const float* __restrict__ vw) {
    extern __shared__ char smc[];
    const uint32_t sb = smem_u32(smc);
    const int tid  = threadIdx.x;
    const int lane = tid & 31;
    const int warp = tid >> 5;
    const int wm   = warp >> 1;              // 0..3
    const int wn   = warp & 1;               // 0..1
    const int n0   = blockIdx.x * 128;
    const int m0   = blockIdx.y * 128;

    const int rr = tid >> 3, cc = tid & 7;
    const char* pa = (const char*)(g_ench + (size_t)(m0 + rr) * 1024 + cc * 8);
    const char* pb = (const char*)(g_Bth  + (size_t)(n0 + rr) * 1024 + cc * 8);
    const uint32_t dA = sb + (uint32_t)((cc >> 2) * PAN + rr * 64 + (cc & 3) * 16);
    const uint32_t dB = dA + 2 * PAN;

#define LOAD_STAGE(kt, st)                                                      \
    do {                                                                        \
        const uint32_t so = (uint32_t)(st) * STGB;                              \
        const int kb_ = (kt) * 128;  /* BK=64 halfs = 128 B */                  \
        _Pragma("unroll")                                                       \
        for (int i_ = 0; i_ < 4; i_++) {                                        \
            asm volatile("cp.async.cg.shared.global [%0], [%1], 16;"            \
                         :: "r"(dA + so + i_ * 2048), "l"(pa + kb_ + i_ * 65536)); \
            asm volatile("cp.async.cg.shared.global [%0], [%1], 16;"            \
                         :: "r"(dB + so + i_ * 2048), "l"(pb + kb_ + i_ * 65536)); \
        }                                                                       \
    } while (0)

    float acc[2][8][4];
#pragma unroll
    for (int i = 0; i < 2; i++)
#pragma unroll
        for (int j = 0; j < 8; j++)
#pragma unroll
            for (int c = 0; c < 4; c++) acc[i][j][c] = 0.f;

    LOAD_STAGE(0, 0);
    asm volatile("cp.async.commit_group;" ::: "memory");
    LOAD_STAGE(1, 1);
    asm volatile("cp.async.commit_group;" ::: "memory");

    const uint32_t koff = (lane & 3) * 16;
    const uint32_t aoff = (uint32_t)(wm * 32 + (lane >> 2)) * 64 + koff;
    const uint32_t boff = (uint32_t)(wn * 64 + (lane >> 2)) * 64 + koff + 2 * PAN;

#pragma unroll
    for (int kt = 0; kt < 16; kt++) {
        const int st = kt % 3;
        asm volatile("cp.async.wait_group 1;" ::: "memory");
        __syncthreads();

        if (kt < 14) LOAD_STAGE(kt + 2, (kt + 2) % 3);
        asm volatile("cp.async.commit_group;" ::: "memory");

        const uint32_t Astg = sb + (uint32_t)st * STGB;

#pragma unroll
        for (int s = 0; s < 2; s++) {           // two k32 panels
            const uint32_t Asb = Astg + (uint32_t)s * PAN + aoff;
            const uint32_t Bsb = Astg + (uint32_t)s * PAN + boff;

            uint32_t ah[4][4];
#pragma unroll
            for (int rdx = 0; rdx < 4; rdx++)
                asm volatile("ld.shared.v4.u32 {%0,%1,%2,%3}, [%4];"
                             : "=r"(ah[rdx][0]), "=r"(ah[rdx][1]),
                               "=r"(ah[rdx][2]), "=r"(ah[rdx][3])
                             : "r"(Asb + rdx * 512));

#pragma unroll
            for (int jh = 0; jh < 2; jh++) {
                uint32_t bh[4][4];
#pragma unroll
                for (int j = 0; j < 4; j++)
                    asm volatile("ld.shared.v4.u32 {%0,%1,%2,%3}, [%4];"
                                 : "=r"(bh[j][0]), "=r"(bh[j][1]),
                                   "=r"(bh[j][2]), "=r"(bh[j][3])
                                 : "r"(Bsb + (jh * 4 + j) * 512));
#pragma unroll
                for (int i = 0; i < 2; i++)
#pragma unroll
                    for (int j = 0; j < 4; j++)
#pragma unroll
                        for (int u = 0; u < 2; u++) {
                            const int jj = jh * 4 + j;
                            asm volatile(
                                "mma.sync.aligned.m16n8k16.row.col.f32.f16.f16.f32 "
                                "{%0,%1,%2,%3}, {%4,%5,%6,%7}, {%8,%9}, {%0,%1,%2,%3};"
                                : "+f"(acc[i][jj][0]), "+f"(acc[i][jj][1]),
                                  "+f"(acc[i][jj][2]), "+f"(acc[i][jj][3])
                                : "r"(ah[2 * i][2 * u]), "r"(ah[2 * i + 1][2 * u]),
                                  "r"(ah[2 * i][2 * u + 1]), "r"(ah[2 * i + 1][2 * u + 1]),
                                  "r"(bh[j][2 * u]), "r"(bh[j][2 * u + 1]));
                        }
            }
        }
    }
#undef LOAD_STAGE

    // Epilogue: energy = tanh(acc + dec_base[b][col]); score partial = energy . v_w
    const int b = m0 >> 11;
    float eadd[16], vv[16];
#pragma unroll
    for (int j = 0; j < 8; j++)
#pragma unroll
        for (int c = 0; c < 2; c++) {
            const int col = n0 + wn * 64 + j * 8 + (lane & 3) * 2 + c;
            eadd[j * 2 + c] = g_decb[b * ND + col];
            vv[j * 2 + c]   = vw[col];
        }

#pragma unroll
    for (int i = 0; i < 2; i++)
#pragma unroll
        for (int h = 0; h < 2; h++) {
            float p = 0.f;
#pragma unroll
            for (int j = 0; j < 8; j++)
#pragma unroll
                for (int c = 0; c < 2; c++)
                    p += fast_tanh(acc[i][j][h * 2 + c] + eadd[j * 2 + c]) * vv[j * 2 + c];
            p += __shfl_xor_sync(0xffffffffu, p, 1);
            p += __shfl_xor_sync(0xffffffffu, p, 2);
            if ((lane & 3) == 0) {
                const int row = m0 + wm * 32 + i * 16 + h * 8 + (lane >> 2);
                atomicAdd(&g_scores[row], p);
            }
        }
}

// ---------------------------------------------------------------------------
// Kernel 3: FUSED masked-softmax + context.  (R12 configuration)
// ---------------------------------------------------------------------------
__global__ void softmax_context_kernel(const int* __restrict__ mask,
                                       float* __restrict__ attw,
                                       float* __restrict__ ctx) {
    const int b   = blockIdx.y;
    const int ch  = blockIdx.x;
    const int tid = threadIdx.x;
    __shared__ float red[256];
    __shared__ float ws[128];
    __shared__ float part[128 * 8];

    // ---- phase 1: full-row masked softmax (redundant per chunk-block)
    const int sbase = tid * 8;
    const float4 sv0 = *(const float4*)(g_scores + b * SS + sbase);
    const float4 sv1 = *(const float4*)(g_scores + b * SS + sbase + 4);
    const int4   mv0 = *(const int4*)(mask + b * SS + sbase);
    const int4   mv1 = *(const int4*)(mask + b * SS + sbase + 4);
    float ls[8];
    ls[0] = mv0.x ? sv0.x : -1e9f;
    ls[1] = mv0.y ? sv0.y : -1e9f;
    ls[2] = mv0.z ? sv0.z : -1e9f;
    ls[3] = mv0.w ? sv0.w : -1e9f;
    ls[4] = mv1.x ? sv1.x : -1e9f;
    ls[5] = mv1.y ? sv1.y : -1e9f;
    ls[6] = mv1.z ? sv1.z : -1e9f;
    ls[7] = mv1.w ? sv1.w : -1e9f;

    float mx = ls[0];
#pragma unroll
    for (int i = 1; i < 8; i++) mx = fmaxf(mx, ls[i]);
    red[tid] = mx;
    __syncthreads();
    for (int off = 128; off > 0; off >>= 1) {
        if (tid < off) red[tid] = fmaxf(red[tid], red[tid + off]);
        __syncthreads();
    }
    mx = red[0];
    __syncthreads();

    float ex[8];
    float sum = 0.f;
#pragma unroll
    for (int i = 0; i < 8; i++) {
        ex[i] = __expf(ls[i] - mx);
        sum += ex[i];
    }
    red[tid] = sum;
    __syncthreads();
    for (int off = 128; off > 0; off >>= 1) {
        if (tid < off) red[tid] += red[tid + off];
        __syncthreads();
    }
    const float inv = 1.f / red[0];

    // owning threads of this chunk write attw + smem weights
    if ((tid >> 4) == ch) {
        float4 lo = make_float4(ex[0] * inv, ex[1] * inv, ex[2] * inv, ex[3] * inv);
        float4 hi = make_float4(ex[4] * inv, ex[5] * inv, ex[6] * inv, ex[7] * inv);
        *(float4*)(attw + b * SS + sbase)     = lo;
        *(float4*)(attw + b * SS + sbase + 4) = hi;
        const int ls0 = sbase - ch * 128;     // 0..120
        *(float4*)(ws + ls0)     = lo;
        *(float4*)(ws + ls0 + 4) = hi;
    }
    __syncthreads();

    // ---- phase 2: context partial for chunk [ch*128, +128)
    const int colg = (tid & 127) * 8;
    const int sh   = tid >> 7;                // s-half 0/1
    const __half* base =
        g_ench + ((size_t)b * SS + ch * 128 + sh * 64) * 1024 + colg;

    float a0 = 0.f, a1 = 0.f, a2 = 0.f, a3 = 0.f;
    float a4 = 0.f, a5 = 0.f, a6 = 0.f, a7 = 0.f;
#pragma unroll 4
    for (int s = 0; s < 64; s++) {
        const uint4 u = *(const uint4*)(base + (size_t)s * 1024);
        const float wv = ws[sh * 64 + s];
        const float2 f0 = __half22float2(*(const __half2*)&u.x);
        const float2 f1 = __half22float2(*(const __half2*)&u.y);
        const float2 f2 = __half22float2(*(const __half2*)&u.z);
        const float2 f3 = __half22float2(*(const __half2*)&u.w);
        a0 += wv * f0.x; a1 += wv * f0.y;
        a2 += wv * f1.x; a3 += wv * f1.y;
        a4 += wv * f2.x; a5 += wv * f2.y;
        a6 += wv * f3.x; a7 += wv * f3.y;
    }

    if (sh == 1) {
        float* p = part + (tid & 127) * 8;
        p[0] = a0; p[1] = a1; p[2] = a2; p[3] = a3;
        p[4] = a4; p[5] = a5; p[6] = a6; p[7] = a7;
    }
    __syncthreads();
    if (sh == 0) {
        const float* p = part + tid * 8;
        float* o = ctx + b * ND + colg;
        atomicAdd(o + 0, a0 + p[0]);
        atomicAdd(o + 1, a1 + p[1]);
        atomicAdd(o + 2, a2 + p[2]);
        atomicAdd(o + 3, a3 + p[3]);
        atomicAdd(o + 4, a4 + p[4]);
        atomicAdd(o + 5, a5 + p[5]);
        atomicAdd(o + 6, a6 + p[6]);
        atomicAdd(o + 7, a7 + p[7]);
    }
}

// ---------------------------------------------------------------------------
extern "C" void kernel_launch(void* const* d_in, const int* in_sizes, int n_in,
                              void* d_out, int out_size) {
    const float* dh   = (const float*)d_in[0];   // (32, 1024)
    const float* enc  = (const float*)d_in[1];   // (32, 2048, 1024)
    const int*   mask = (const int*)d_in[2];     // (32, 2048)
    const float* W    = (const float*)d_in[3];   // (2048, 1024)
    const float* ba   = (const float*)d_in[4];   // (1024,)
    const float* vw   = (const float*)d_in[5];   // (1024,)

    float* out  = (float*)d_out;
    float* ctx  = out;                 // (32, 1024)
    float* attw = out + BB * ND;       // (32, 2048)

    cudaFuncSetAttribute(score_gemm, cudaFuncAttributeMaxDynamicSharedMemorySize, GEMM_SMEM);

    pre_kernel<<<5248, 256>>>(enc, W, dh, ba, ctx);
    score_gemm<<<dim3(8, 512), 256, GEMM_SMEM>>>(vw);
    softmax_context_kernel<<<dim3(16, 32), 256>>>(mask, attw, ctx);
}

// round 14
// speedup vs baseline: 1.1029x; 1.0012x over previous
#include <cuda_runtime.h>
#include <cuda_fp16.h>
#include <cstdint>

#define BB   32
#define SS   2048
#define ND   1024

// Scratch (allocation-free rule: __device__ globals)
__device__ float  g_scores[BB * SS];
__device__ float  g_decb[BB * ND];
__device__ __half g_Bth[ND * ND];         // W_enc^T fp16: Bth[n][k] = W[1024+k][n]
__device__ __half g_ench[BB * SS * ND];   // encoder_outputs in fp16

// ---------------------------------------------------------------- helpers
__device__ __forceinline__ float fast_tanh(float x) {
    float y;
    asm("tanh.approx.f32 %0, %1;" : "=f"(y) : "f"(x));
    return y;
}
__device__ __forceinline__ uint32_t smem_u32(const void* p) {
    uint32_t a;
    asm("{ .reg .u64 t; cvta.to.shared.u64 t, %1; cvt.u32.u64 %0, t; }" : "=r"(a) : "l"(p));
    return a;
}

// ---------------------------------------------------------------------------
// Kernel P: fused prologue (latency-bound branches FIRST so their tails hide
// under the bandwidth-bound convert wave).
//   blocks [0,128)      : dec_base = dh @ W_dec + b_attn; zero scratch + ctx
//   blocks [128,1152)   : transpose W_enc -> g_Bth fp16
//   blocks [1152,33920) : convert enc fp32 -> g_ench fp16, ONE uint4/thread
//                         (no unroll -> low regs -> high occupancy -> MLP
//                          from resident warps, not serialized unroll)
// ---------------------------------------------------------------------------
__global__ void pre_kernel(const float* __restrict__ enc,
                           const float* __restrict__ W,
                           const float* __restrict__ dh,
                           const float* __restrict__ b_attn,
                           float* __restrict__ out_ctx) {
    __shared__ float shb[1088];
    const int bid = blockIdx.x;
    const int tid = threadIdx.x;

    if (bid >= 1152) {
        // convert: 8M uint4 outputs; 32768 blocks x 256 threads x 1
        const uint32_t o4 = (uint32_t)(bid - 1152) * 256 + tid;
        const float4 v0 = *(const float4*)(enc + (size_t)o4 * 8);
        const float4 v1 = *(const float4*)(enc + (size_t)o4 * 8 + 4);
        __half2 h0 = __floats2half2_rn(v0.x, v0.y);
        __half2 h1 = __floats2half2_rn(v0.z, v0.w);
        __half2 h2 = __floats2half2_rn(v1.x, v1.y);
        __half2 h3 = __floats2half2_rn(v1.z, v1.w);
        uint4 o;
        o.x = *(uint32_t*)&h0;
        o.y = *(uint32_t*)&h1;
        o.z = *(uint32_t*)&h2;
        o.w = *(uint32_t*)&h3;
        ((uint4*)g_ench)[o4] = o;
    } else if (bid < 128) {
        const int b = bid >> 2, dc = bid & 3;

        for (int i = bid * 256 + tid; i < BB * SS; i += 128 * 256) g_scores[i] = 0.f;
        for (int i = bid * 256 + tid; i < BB * ND; i += 128 * 256) out_ctx[i] = 0.f;

        for (int i = tid; i < ND; i += 256) shb[i] = dh[b * ND + i];
        __syncthreads();

        const int d0 = dc * 256 + tid;
        float a = b_attn[d0];
#pragma unroll 8
        for (int e = 0; e < ND; e++)
            a += shb[e] * W[(size_t)e * ND + d0];
        g_decb[b * ND + d0] = a;
    } else {
        const int bid2 = bid - 128;
        const int kb = (bid2 & 31) * 32, nb = (bid2 >> 5) * 32;
        const int tx = tid & 31, ty = tid >> 5;           // ty 0..7
        float (*t)[33] = (float(*)[33])shb;
#pragma unroll
        for (int i = 0; i < 32; i += 8)
            t[ty + i][tx] = W[(size_t)(1024 + kb + ty + i) * 1024 + nb + tx];
        __syncthreads();
#pragma unroll
        for (int i = 0; i < 32; i += 8)
            g_Bth[(size_t)(nb + ty + i) * 1024 + kb + tx] = __float2half_rn(t[tx][ty + i]);
    }
}

// ---------------------------------------------------------------------------
// Kernel 2: enc_proj GEMM, fp16 mma.sync m16n8k16, 128x128 tile, BK=64,
//   3-stage cp.async ring (96KB), ONE sync per BK=64, FULL unroll (16 iters),
//   fused tanh + v-dot.   (R10 configuration — best measured)
// ---------------------------------------------------------------------------
#define PAN       8192
#define STGB      (4 * PAN)                // 32 KB per stage
#define GEMM_SMEM (3 * STGB)               // 96 KB

__global__ __launch_bounds__(256, 2) void score_gemm(const float* __restrict__ vw) {
    extern __shared__ char smc[];
    const uint32_t sb = smem_u32(smc);
    const int tid  = threadIdx.x;
    const int lane = tid & 31;
    const int warp = tid >> 5;
    const int wm   = warp >> 1;              // 0..3
    const int wn   = warp & 1;               // 0..1
    const int n0   = blockIdx.x * 128;
    const int m0   = blockIdx.y * 128;

    const int rr = tid >> 3, cc = tid & 7;
    const char* pa = (const char*)(g_ench + (size_t)(m0 + rr) * 1024 + cc * 8);
    const char* pb = (const char*)(g_Bth  + (size_t)(n0 + rr) * 1024 + cc * 8);
    const uint32_t dA = sb + (uint32_t)((cc >> 2) * PAN + rr * 64 + (cc & 3) * 16);
    const uint32_t dB = dA + 2 * PAN;

#define LOAD_STAGE(kt, st)                                                      \
    do {                                                                        \
        const uint32_t so = (uint32_t)(st) * STGB;                              \
        const int kb_ = (kt) * 128;  /* BK=64 halfs = 128 B */                  \
        _Pragma("unroll")                                                       \
        for (int i_ = 0; i_ < 4; i_++) {                                        \
            asm volatile("cp.async.cg.shared.global [%0], [%1], 16;"            \
                         :: "r"(dA + so + i_ * 2048), "l"(pa + kb_ + i_ * 65536)); \
            asm volatile("cp.async.cg.shared.global [%0], [%1], 16;"            \
                         :: "r"(dB + so + i_ * 2048), "l"(pb + kb_ + i_ * 65536)); \
        }                                                                       \
    } while (0)

    float acc[2][8][4];
#pragma unroll
    for (int i = 0; i < 2; i++)
#pragma unroll
        for (int j = 0; j < 8; j++)
#pragma unroll
            for (int c = 0; c < 4; c++) acc[i][j][c] = 0.f;

    LOAD_STAGE(0, 0);
    asm volatile("cp.async.commit_group;" ::: "memory");
    LOAD_STAGE(1, 1);
    asm volatile("cp.async.commit_group;" ::: "memory");

    const uint32_t koff = (lane & 3) * 16;
    const uint32_t aoff = (uint32_t)(wm * 32 + (lane >> 2)) * 64 + koff;
    const uint32_t boff = (uint32_t)(wn * 64 + (lane >> 2)) * 64 + koff + 2 * PAN;

#pragma unroll
    for (int kt = 0; kt < 16; kt++) {
        const int st = kt % 3;
        asm volatile("cp.async.wait_group 1;" ::: "memory");
        __syncthreads();

        if (kt < 14) LOAD_STAGE(kt + 2, (kt + 2) % 3);
        asm volatile("cp.async.commit_group;" ::: "memory");

        const uint32_t Astg = sb + (uint32_t)st * STGB;

#pragma unroll
        for (int s = 0; s < 2; s++) {           // two k32 panels
            const uint32_t Asb = Astg + (uint32_t)s * PAN + aoff;
            const uint32_t Bsb = Astg + (uint32_t)s * PAN + boff;

            uint32_t ah[4][4];
#pragma unroll
            for (int rdx = 0; rdx < 4; rdx++)
                asm volatile("ld.shared.v4.u32 {%0,%1,%2,%3}, [%4];"
                             : "=r"(ah[rdx][0]), "=r"(ah[rdx][1]),
                               "=r"(ah[rdx][2]), "=r"(ah[rdx][3])
                             : "r"(Asb + rdx * 512));

#pragma unroll
            for (int jh = 0; jh < 2; jh++) {
                uint32_t bh[4][4];
#pragma unroll
                for (int j = 0; j < 4; j++)
                    asm volatile("ld.shared.v4.u32 {%0,%1,%2,%3}, [%4];"
                                 : "=r"(bh[j][0]), "=r"(bh[j][1]),
                                   "=r"(bh[j][2]), "=r"(bh[j][3])
                                 : "r"(Bsb + (jh * 4 + j) * 512));
#pragma unroll
                for (int i = 0; i < 2; i++)
#pragma unroll
                    for (int j = 0; j < 4; j++)
#pragma unroll
                        for (int u = 0; u < 2; u++) {
                            const int jj = jh * 4 + j;
                            asm volatile(
                                "mma.sync.aligned.m16n8k16.row.col.f32.f16.f16.f32 "
                                "{%0,%1,%2,%3}, {%4,%5,%6,%7}, {%8,%9}, {%0,%1,%2,%3};"
                                : "+f"(acc[i][jj][0]), "+f"(acc[i][jj][1]),
                                  "+f"(acc[i][jj][2]), "+f"(acc[i][jj][3])
                                : "r"(ah[2 * i][2 * u]), "r"(ah[2 * i + 1][2 * u]),
                                  "r"(ah[2 * i][2 * u + 1]), "r"(ah[2 * i + 1][2 * u + 1]),
                                  "r"(bh[j][2 * u]), "r"(bh[j][2 * u + 1]));
                        }
            }
        }
    }
#undef LOAD_STAGE

    // Epilogue: energy = tanh(acc + dec_base[b][col]); score partial = energy . v_w
    const int b = m0 >> 11;
    float eadd[16], vv[16];
#pragma unroll
    for (int j = 0; j < 8; j++)
#pragma unroll
        for (int c = 0; c < 2; c++) {
            const int col = n0 + wn * 64 + j * 8 + (lane & 3) * 2 + c;
            eadd[j * 2 + c] = g_decb[b * ND + col];
            vv[j * 2 + c]   = vw[col];
        }

#pragma unroll
    for (int i = 0; i < 2; i++)
#pragma unroll
        for (int h = 0; h < 2; h++) {
            float p = 0.f;
#pragma unroll
            for (int j = 0; j < 8; j++)
#pragma unroll
                for (int c = 0; c < 2; c++)
                    p += fast_tanh(acc[i][j][h * 2 + c] + eadd[j * 2 + c]) * vv[j * 2 + c];
            p += __shfl_xor_sync(0xffffffffu, p, 1);
            p += __shfl_xor_sync(0xffffffffu, p, 2);
            if ((lane & 3) == 0) {
                const int row = m0 + wm * 32 + i * 16 + h * 8 + (lane >> 2);
                atomicAdd(&g_scores[row], p);
            }
        }
}

// ---------------------------------------------------------------------------
// Kernel 3: FUSED masked-softmax + context.  (R12 configuration)
// ---------------------------------------------------------------------------
__global__ void softmax_context_kernel(const int* __restrict__ mask,
                                       float* __restrict__ attw,
                                       float* __restrict__ ctx) {
    const int b   = blockIdx.y;
    const int ch  = blockIdx.x;
    const int tid = threadIdx.x;
    __shared__ float red[256];
    __shared__ float ws[128];
    __shared__ float part[128 * 8];

    // ---- phase 1: full-row masked softmax (redundant per chunk-block)
    const int sbase = tid * 8;
    const float4 sv0 = *(const float4*)(g_scores + b * SS + sbase);
    const float4 sv1 = *(const float4*)(g_scores + b * SS + sbase + 4);
    const int4   mv0 = *(const int4*)(mask + b * SS + sbase);
    const int4   mv1 = *(const int4*)(mask + b * SS + sbase + 4);
    float ls[8];
    ls[0] = mv0.x ? sv0.x : -1e9f;
    ls[1] = mv0.y ? sv0.y : -1e9f;
    ls[2] = mv0.z ? sv0.z : -1e9f;
    ls[3] = mv0.w ? sv0.w : -1e9f;
    ls[4] = mv1.x ? sv1.x : -1e9f;
    ls[5] = mv1.y ? sv1.y : -1e9f;
    ls[6] = mv1.z ? sv1.z : -1e9f;
    ls[7] = mv1.w ? sv1.w : -1e9f;

    float mx = ls[0];
#pragma unroll
    for (int i = 1; i < 8; i++) mx = fmaxf(mx, ls[i]);
    red[tid] = mx;
    __syncthreads();
    for (int off = 128; off > 0; off >>= 1) {
        if (tid < off) red[tid] = fmaxf(red[tid], red[tid + off]);
        __syncthreads();
    }
    mx = red[0];
    __syncthreads();

    float ex[8];
    float sum = 0.f;
#pragma unroll
    for (int i = 0; i < 8; i++) {
        ex[i] = __expf(ls[i] - mx);
        sum += ex[i];
    }
    red[tid] = sum;
    __syncthreads();
    for (int off = 128; off > 0; off >>= 1) {
        if (tid < off) red[tid] += red[tid + off];
        __syncthreads();
    }
    const float inv = 1.f / red[0];

    // owning threads of this chunk write attw + smem weights
    if ((tid >> 4) == ch) {
        float4 lo = make_float4(ex[0] * inv, ex[1] * inv, ex[2] * inv, ex[3] * inv);
        float4 hi = make_float4(ex[4] * inv, ex[5] * inv, ex[6] * inv, ex[7] * inv);
        *(float4*)(attw + b * SS + sbase)     = lo;
        *(float4*)(attw + b * SS + sbase + 4) = hi;
        const int ls0 = sbase - ch * 128;     // 0..120
        *(float4*)(ws + ls0)     = lo;
        *(float4*)(ws + ls0 + 4) = hi;
    }
    __syncthreads();

    // ---- phase 2: context partial for chunk [ch*128, +128)
    const int colg = (tid & 127) * 8;
    const int sh   = tid >> 7;                // s-half 0/1
    const __half* base =
        g_ench + ((size_t)b * SS + ch * 128 + sh * 64) * 1024 + colg;

    float a0 = 0.f, a1 = 0.f, a2 = 0.f, a3 = 0.f;
    float a4 = 0.f, a5 = 0.f, a6 = 0.f, a7 = 0.f;
#pragma unroll 4
    for (int s = 0; s < 64; s++) {
        const uint4 u = *(const uint4*)(base + (size_t)s * 1024);
        const float wv = ws[sh * 64 + s];
        const float2 f0 = __half22float2(*(const __half2*)&u.x);
        const float2 f1 = __half22float2(*(const __half2*)&u.y);
        const float2 f2 = __half22float2(*(const __half2*)&u.z);
        const float2 f3 = __half22float2(*(const __half2*)&u.w);
        a0 += wv * f0.x; a1 += wv * f0.y;
        a2 += wv * f1.x; a3 += wv * f1.y;
        a4 += wv * f2.x; a5 += wv * f2.y;
        a6 += wv * f3.x; a7 += wv * f3.y;
    }

    if (sh == 1) {
        float* p = part + (tid & 127) * 8;
        p[0] = a0; p[1] = a1; p[2] = a2; p[3] = a3;
        p[4] = a4; p[5] = a5; p[6] = a6; p[7] = a7;
    }
    __syncthreads();
    if (sh == 0) {
        const float* p = part + tid * 8;
        float* o = ctx + b * ND + colg;
        atomicAdd(o + 0, a0 + p[0]);
        atomicAdd(o + 1, a1 + p[1]);
        atomicAdd(o + 2, a2 + p[2]);
        atomicAdd(o + 3, a3 + p[3]);
        atomicAdd(o + 4, a4 + p[4]);
        atomicAdd(o + 5, a5 + p[5]);
        atomicAdd(o + 6, a6 + p[6]);
        atomicAdd(o + 7, a7 + p[7]);
    }
}

// ---------------------------------------------------------------------------
extern "C" void kernel_launch(void* const* d_in, const int* in_sizes, int n_in,
                              void* d_out, int out_size) {
    const float* dh   = (const float*)d_in[0];   // (32, 1024)
    const float* enc  = (const float*)d_in[1];   // (32, 2048, 1024)
    const int*   mask = (const int*)d_in[2];     // (32, 2048)
    const float* W    = (const float*)d_in[3];   // (2048, 1024)
    const float* ba   = (const float*)d_in[4];   // (1024,)
    const float* vw   = (const float*)d_in[5];   // (1024,)

    float* out  = (float*)d_out;
    float* ctx  = out;                 // (32, 1024)
    float* attw = out + BB * ND;       // (32, 2048)

    cudaFuncSetAttribute(score_gemm, cudaFuncAttributeMaxDynamicSharedMemorySize, GEMM_SMEM);

    pre_kernel<<<33920, 256>>>(enc, W, dh, ba, ctx);
    score_gemm<<<dim3(8, 512), 256, GEMM_SMEM>>>(vw);
    softmax_context_kernel<<<dim3(16, 32), 256>>>(mask, attw, ctx);
}